// round 1
// baseline (speedup 1.0000x reference)
#include <cuda_runtime.h>
#include <stdint.h>

#define BATCH 16
#define CIN   128
#define HH    128
#define WW    128
#define OCH   256
#define HW    (HH*WW)
#define KTOT  1152.0f   // C*3*3
#define BADCNT 576.0f   // 0.5 * 1152

// scratch (no allocations allowed)
__device__ float g_csum[BATCH*HW];
__device__ float g_ccnt[BATCH*HW];
__device__ float g_pm  [BATCH*HW];
__device__ float g_bad [BATCH*HW];

__device__ __forceinline__ bool nan_bits(float v) {
    return (__float_as_uint(v) & 0x7fffffffu) > 0x7f800000u;
}

// ---------------------------------------------------------------------------
// Kernel 1: per-(b,h,w) channel reduction: sum of non-NaN values, NaN count
// ---------------------------------------------------------------------------
__global__ void stats1_kernel(const float* __restrict__ x) {
    int idx = blockIdx.x * blockDim.x + threadIdx.x;
    if (idx >= BATCH * HW) return;
    int b  = idx / HW;
    int hw = idx - b * HW;
    const float* xp = x + (size_t)b * CIN * HW + hw;
    float s = 0.f, cnt = 0.f;
    #pragma unroll 8
    for (int c = 0; c < CIN; c++) {
        float v = xp[(size_t)c * HW];
        bool n = nan_bits(v);
        cnt += n ? 1.f : 0.f;
        s   += n ? 0.f : v;
    }
    g_csum[idx] = s;
    g_ccnt[idx] = cnt;
}

// ---------------------------------------------------------------------------
// Kernel 2: 3x3 box sum (zero pad) -> patch_mean, bad flag
// ---------------------------------------------------------------------------
__global__ void stats2_kernel() {
    int idx = blockIdx.x * blockDim.x + threadIdx.x;
    if (idx >= BATCH * HW) return;
    int b  = idx / HW;
    int hw = idx - b * HW;
    int oh = hw / WW;
    int ow = hw - oh * WW;
    float vs = 0.f, cnt = 0.f;
    #pragma unroll
    for (int kh = -1; kh <= 1; kh++) {
        int ih = oh + kh;
        if (ih < 0 || ih >= HH) continue;
        #pragma unroll
        for (int kw = -1; kw <= 1; kw++) {
            int iw = ow + kw;
            if (iw < 0 || iw >= WW) continue;
            int g = b * HW + ih * WW + iw;
            vs  += g_csum[g];
            cnt += g_ccnt[g];
        }
    }
    float valid = KTOT - cnt;
    g_pm[idx]  = vs / fmaxf(valid, 1.f);
    g_bad[idx] = (cnt >= BADCNT) ? 1.f : 0.f;
}

// ---------------------------------------------------------------------------
// Kernel 3: main conv as implicit GEMM over substituted values
//   block: 8x8 output pixels x 64 output channels
//   K loop: chunks of 8 input channels (72 k-values)
// ---------------------------------------------------------------------------
#define TPX 8
#define TPY 8
#define NPX 64            // pixels per block
#define TOC 64            // output channels per block
#define CCH 8             // channels per chunk
#define KK  (CCH*9)       // 72

__global__ __launch_bounds__(256, 4)
void conv_main_kernel(const float* __restrict__ x,
                      const float* __restrict__ w,
                      const float* __restrict__ bias,
                      float* __restrict__ out)
{
    __shared__ float xs[CCH][TPY+2][TPX+2];   // raw input tile (0-padded, NaNs kept)
    __shared__ float ys[KK][NPX];             // substituted A-tile [k][pixel]
    __shared__ float ws[KK][TOC];             // B-tile [k][oc]
    __shared__ float pms[NPX];
    __shared__ float bads[NPX];

    const int ow0 = blockIdx.x * TPX;
    const int oh0 = blockIdx.y * TPY;
    const int bz  = blockIdx.z;
    const int b   = bz >> 2;
    const int oc0 = (bz & 3) * TOC;
    const int t   = threadIdx.x;

    if (t < NPX) {
        int py = t >> 3, px = t & 7;
        int g = b * HW + (oh0 + py) * WW + (ow0 + px);
        pms[t]  = g_pm[g];
        bads[t] = g_bad[g];
    }

    const int tx = t & 15;   // pixel group (4 pixels)
    const int ty = t >> 4;   // oc group (4 ocs)

    float acc[4][4];
    #pragma unroll
    for (int i = 0; i < 4; i++)
        #pragma unroll
        for (int j = 0; j < 4; j++) acc[i][j] = 0.f;

    for (int c0 = 0; c0 < CIN; c0 += CCH) {
        __syncthreads();   // previous GEMM done reading ys/ws

        // load raw x tile (10x10xCCH), zero-padded OOB
        for (int i = t; i < CCH * 10 * 10; i += 256) {
            int cc = i / 100;
            int r  = i - cc * 100;
            int ih = r / 10, iw = r - (r / 10) * 10;
            int gh = oh0 + ih - 1, gw = ow0 + iw - 1;
            float v = 0.f;
            if (gh >= 0 && gh < HH && gw >= 0 && gw < WW)
                v = x[((size_t)(b * CIN + c0 + cc)) * HW + gh * WW + gw];
            xs[cc][ih][iw] = v;
        }
        // load weight tile [64 oc][72 k] -> ws[k][oc]
        for (int i = t; i < TOC * KK; i += 256) {
            int oc = i / KK;
            int kk = i - oc * KK;
            ws[kk][oc] = w[(size_t)(oc0 + oc) * (CIN * 9) + c0 * 9 + kk];
        }
        __syncthreads();

        // build substituted y tile: y = isnan(x) ? patch_mean(pixel) : x
        for (int i = t; i < KK * NPX; i += 256) {
            int k = i >> 6;           // /64
            int p = i & 63;
            int cc = k / 9;
            int r  = k - cc * 9;
            int kh = r / 3, kw = r - (r / 3) * 3;
            int py = p >> 3, px = p & 7;
            float xr = xs[cc][py + kh][px + kw];
            ys[k][p] = nan_bits(xr) ? pms[p] : xr;
        }
        __syncthreads();

        // 64x64x72 register-tiled GEMM
        #pragma unroll 8
        for (int k = 0; k < KK; k++) {
            float4 yv = *(const float4*)&ys[k][tx * 4];
            float4 wv = *(const float4*)&ws[k][ty * 4];
            float yy[4] = {yv.x, yv.y, yv.z, yv.w};
            float wwv[4] = {wv.x, wv.y, wv.z, wv.w};
            #pragma unroll
            for (int i = 0; i < 4; i++)
                #pragma unroll
                for (int j = 0; j < 4; j++)
                    acc[i][j] += yy[i] * wwv[j];
        }
    }

    // epilogue: add bias, force NaN where bad; vectorized stores (4 consecutive ow)
    const float NANF = __uint_as_float(0x7fc00000u);
    int p0 = tx * 4;
    int py = p0 >> 3, px0 = p0 & 7;           // 4 consecutive pixels share a row
    int oh = oh0 + py, ow = ow0 + px0;
    #pragma unroll
    for (int j = 0; j < 4; j++) {
        int oc = oc0 + ty * 4 + j;
        float bv = bias[oc];
        float4 o;
        float v0 = acc[0][j] + bv;
        float v1 = acc[1][j] + bv;
        float v2 = acc[2][j] + bv;
        float v3 = acc[3][j] + bv;
        o.x = (bads[p0 + 0] != 0.f) ? NANF : v0;
        o.y = (bads[p0 + 1] != 0.f) ? NANF : v1;
        o.z = (bads[p0 + 2] != 0.f) ? NANF : v2;
        o.w = (bads[p0 + 3] != 0.f) ? NANF : v3;
        *(float4*)&out[(((size_t)b * OCH + oc) * HH + oh) * WW + ow] = o;
    }
}

// ---------------------------------------------------------------------------
extern "C" void kernel_launch(void* const* d_in, const int* in_sizes, int n_in,
                              void* d_out, int out_size) {
    const float* x    = (const float*)d_in[0];
    const float* wk   = (const float*)d_in[1];
    const float* bias = (const float*)d_in[2];
    float* out        = (float*)d_out;

    int npix = BATCH * HW;
    stats1_kernel<<<(npix + 255) / 256, 256>>>(x);
    stats2_kernel<<<(npix + 255) / 256, 256>>>();

    dim3 grid(WW / TPX, HH / TPY, BATCH * (OCH / TOC));
    conv_main_kernel<<<grid, 256>>>(x, wk, bias, out);
}

// round 6
// speedup vs baseline: 6.2438x; 6.2438x over previous
#include <cuda_runtime.h>
#include <cuda_fp16.h>
#include <stdint.h>

#define BATCH 16
#define CIN   128
#define HH    128
#define WW    128
#define OCH   256
#define HW    (HH*WW)
#define KTOT  1152.0f
#define BADCNT 576.0f

// ---------------- scratch (no allocations allowed) ----------------
__device__ float g_pm  [BATCH*HW];
__device__ float g_bad [BATCH*HW];
__device__ float g_csum[BATCH*HW];
__device__ float g_ccnt[BATCH*HW];
// B fragments, pre-formatted for mma.sync m16n8k16:
// [ (tap*4+cg)*2+nh ][ chain2 ][ nt16 ][ kt2 ][ lane32 ][ reg2 ]  (u32 = 2 fp16)
// per-tcn block = 4096 words = 16384 bytes
#define WF_WORDS (72*2*16*2*32*2)
__device__ uint32_t g_wf[WF_WORDS];

__device__ __forceinline__ bool nan_bits(float v) {
    return (__float_as_uint(v) & 0x7fffffffu) > 0x7f800000u;
}
__device__ __forceinline__ uint32_t smem_u32(const void* p) {
    return (uint32_t)__cvta_generic_to_shared(p);
}
__device__ __forceinline__ void cp16(uint32_t dst, const void* src) {
    asm volatile("cp.async.cg.shared.global [%0], [%1], 16;" :: "r"(dst), "l"(src));
}
__device__ __forceinline__ void mma16816(float* c, const uint32_t* a, const uint32_t* b) {
    asm volatile(
        "mma.sync.aligned.m16n8k16.row.col.f32.f16.f16.f32 "
        "{%0,%1,%2,%3}, {%4,%5,%6,%7}, {%8,%9}, {%0,%1,%2,%3};"
        : "+f"(c[0]), "+f"(c[1]), "+f"(c[2]), "+f"(c[3])
        : "r"(a[0]), "r"(a[1]), "r"(a[2]), "r"(a[3]), "r"(b[0]), "r"(b[1]));
}

// ---------------- stats kernels ----------------
__global__ void stats1_kernel(const float* __restrict__ x) {
    int idx = blockIdx.x * blockDim.x + threadIdx.x;
    if (idx >= BATCH * HW) return;
    int b  = idx / HW;
    int hw = idx - b * HW;
    const float* xp = x + (size_t)b * CIN * HW + hw;
    float s = 0.f, cnt = 0.f;
    #pragma unroll 8
    for (int c = 0; c < CIN; c++) {
        float v = xp[(size_t)c * HW];
        bool n = nan_bits(v);
        cnt += n ? 1.f : 0.f;
        s   += n ? 0.f : v;
    }
    g_csum[idx] = s;
    g_ccnt[idx] = cnt;
}

__global__ void stats2_kernel() {
    int idx = blockIdx.x * blockDim.x + threadIdx.x;
    if (idx >= BATCH * HW) return;
    int b  = idx / HW;
    int hw = idx - b * HW;
    int oh = hw / WW;
    int ow = hw - oh * WW;
    float vs = 0.f, cnt = 0.f;
    #pragma unroll
    for (int kh = -1; kh <= 1; kh++) {
        int ih = oh + kh;
        if (ih < 0 || ih >= HH) continue;
        #pragma unroll
        for (int kw = -1; kw <= 1; kw++) {
            int iw = ow + kw;
            if (iw < 0 || iw >= WW) continue;
            int g = b * HW + ih * WW + iw;
            vs  += g_csum[g];
            cnt += g_ccnt[g];
        }
    }
    float valid = KTOT - cnt;
    g_pm[idx]  = vs / fmaxf(valid, 1.f);
    g_bad[idx] = (cnt >= BADCNT) ? 1.f : 0.f;
}

// ---------------- weight prep: fp16 hi/lo split into mma B-fragment layout ----------------
__global__ void wprep_kernel(const float* __restrict__ w) {
    int idx = blockIdx.x * blockDim.x + threadIdx.x;
    if (idx >= WF_WORDS) return;
    int r     = idx & 1;               // B reg (k-half): b0 k=0..7, b1 k=8..15
    int lane  = (idx >> 1) & 31;
    int kt    = (idx >> 6) & 1;
    int nt    = (idx >> 7) & 15;
    int chain = (idx >> 11) & 1;
    int tcn   = idx >> 12;             // (tap*4+cg)*2+nh
    int nh    = tcn & 1;
    int tapcg = tcn >> 1;
    int cg    = tapcg & 3;
    int tap   = tapcg >> 2;

    int oc = nh * 128 + nt * 8 + (lane >> 2);
    int k0 = (lane & 3) * 2 + r * 8;   // k within 16
    int c0 = cg * 32 + kt * 16 + k0;

    uint32_t pack = 0;
    #pragma unroll
    for (int e = 0; e < 2; e++) {
        float wv = w[((size_t)oc * CIN + (c0 + e)) * 9 + tap];
        __half hi = __float2half_rn(wv);
        __half lo = __float2half_rn(wv - __half2float(hi));
        __half v  = (chain == 0) ? hi : lo;
        pack |= (uint32_t)__half_as_ushort(v) << (e * 16);
    }
    g_wf[idx] = pack;
}

// ---------------- main conv: fp16 mma.sync implicit GEMM ----------------
// CTA: M=128 pixels (one output row) x N=128 ocs (one half). K=1152.
// 8 warps as 2(m) x 4(n); warp tile 64x32; per-thread 4x4 m16n8 tiles.
__global__ __launch_bounds__(256, 2)
void conv_mma_kernel(const float* __restrict__ x,
                     const float* __restrict__ bias,
                     float* __restrict__ out)
{
    __shared__ float    s_raw[32 * 132];     // one input row, 32 channels, padded width
    __shared__ uint32_t s_af[2048];          // A frags [mt8*kt2][lane32][reg4]
    __shared__ uint32_t s_bf[4096];          // B frags [chain2][nt16][kt2][lane32][reg2]
    __shared__ float    s_pm[128], s_bad[128], s_bias[128];

    const int tid  = threadIdx.x;
    const int lane = tid & 31;
    const int wid  = tid >> 5;
    const int oh   = blockIdx.x;
    const int nh   = blockIdx.y;
    const int b    = blockIdx.z;

    if (tid < 128) {
        int g = b * HW + oh * WW + tid;
        s_pm[tid]   = g_pm[g];
        s_bad[tid]  = g_bad[g];
        s_bias[tid] = bias[nh * 128 + tid];
    }

    const int mt0 = (wid >> 2) * 4;   // warp m16-tile base (0 or 4)
    const int nt0 = (wid & 3) * 4;    // warp n8-tile base  (0,4,8,12)

    float acc[4][4][4];
    #pragma unroll
    for (int i = 0; i < 4; i++)
        #pragma unroll
        for (int j = 0; j < 4; j++)
            #pragma unroll
            for (int r = 0; r < 4; r++) acc[i][j][r] = 0.f;

    __syncthreads();  // s_pm ready

    for (int cg = 0; cg < 4; cg++) {
        for (int kh = 0; kh < 3; kh++) {
            // ---- stage raw fp32 row (32 channels x 130 cols, zero-padded) ----
            const int rin = oh + kh - 1;
            const bool rowok = (rin >= 0) & (rin < HH);
            const float* xrow = x + ((size_t)(b * CIN + cg * 32) * HH + rin) * WW;
            for (int i = tid; i < 32 * 132; i += 256) {
                int c  = i / 132;
                int wc = i - c * 132;
                int col = wc - 1;
                float v = 0.f;
                if (rowok && col >= 0 && col < WW)
                    v = xrow[(size_t)c * HW + col];
                s_raw[i] = v;
            }
            __syncthreads();

            for (int kw = 0; kw < 3; kw++) {
                const int tap = kh * 3 + kw;
                // ---- B fragments: raw cp.async, 16384 bytes (pre-formatted) ----
                {
                    const char* src = (const char*)g_wf +
                        ((size_t)((tap * 4 + cg) * 2 + nh) * 16384);
                    uint32_t d = smem_u32(s_bf) + (uint32_t)tid * 16u;
                    cp16(d,         src + tid * 16);
                    cp16(d + 4096,  src + 4096  + tid * 16);
                    cp16(d + 8192,  src + 8192  + tid * 16);
                    cp16(d + 12288, src + 12288 + tid * 16);
                    asm volatile("cp.async.commit_group;");
                }
                // ---- A fragments: substitute + fp16, PTX m16n8k16 frag order ----
                // a0:{m, k}  a1:{m+8, k}  a2:{m, k+8}  a3:{m+8, k+8}
                for (int w = tid; w < 2048; w += 256) {
                    int reg  = w & 3;
                    int ln   = (w >> 2) & 31;
                    int tile = w >> 7;            // mt*2 + kt
                    int kt   = tile & 1;
                    int mt   = tile >> 1;
                    int m    = mt * 16 + ((reg & 1) << 3) + (ln >> 2);
                    int k    = kt * 16 + ((reg >> 1) << 3) + (ln & 3) * 2;
                    float f0 = s_raw[k * 132 + m + kw];
                    float f1 = s_raw[(k + 1) * 132 + m + kw];
                    float pm = s_pm[m];
                    f0 = nan_bits(f0) ? pm : f0;
                    f1 = nan_bits(f1) ? pm : f1;
                    uint32_t h0 = __half_as_ushort(__float2half_rn(f0));
                    uint32_t h1 = __half_as_ushort(__float2half_rn(f1));
                    s_af[w] = (h1 << 16) | h0;
                }
                asm volatile("cp.async.wait_group 0;");
                __syncthreads();

                // ---- MMA: K=32 (2 k16 steps), 2 chains (w_hi, w_lo) ----
                #pragma unroll
                for (int kt = 0; kt < 2; kt++) {
                    uint32_t a[4][4];
                    #pragma unroll
                    for (int i = 0; i < 4; i++) {
                        uint4 av = *(const uint4*)&s_af[(((mt0 + i) * 2 + kt) * 32 + lane) * 4];
                        a[i][0] = av.x; a[i][1] = av.y; a[i][2] = av.z; a[i][3] = av.w;
                    }
                    #pragma unroll
                    for (int ch = 0; ch < 2; ch++) {
                        #pragma unroll
                        for (int j = 0; j < 4; j++) {
                            uint2 bv = *(const uint2*)
                                &s_bf[(((ch * 16 + nt0 + j) * 2 + kt) * 32 + lane) * 2];
                            uint32_t bb[2] = {bv.x, bv.y};
                            #pragma unroll
                            for (int i = 0; i < 4; i++)
                                mma16816(acc[i][j], a[i], bb);
                        }
                    }
                }
                __syncthreads();   // protect s_af/s_bf (and s_raw at kh turn)
            }
        }
    }

    // ---- epilogue: bias + bad->NaN, direct stores ----
    const float NANF = __uint_as_float(0x7fc00000u);
    #pragma unroll
    for (int i = 0; i < 4; i++) {
        #pragma unroll
        for (int r = 0; r < 4; r++) {
            int m = (mt0 + i) * 16 + ((r >> 1) << 3) + (lane >> 2);
            bool isbad = s_bad[m] != 0.f;
            #pragma unroll
            for (int j = 0; j < 4; j++) {
                int n  = (nt0 + j) * 8 + (lane & 3) * 2 + (r & 1);
                int oc = nh * 128 + n;
                float v = acc[i][j][r] + s_bias[n];
                out[(((size_t)b * OCH + oc) * HH + oh) * WW + m] = isbad ? NANF : v;
            }
        }
    }
}

// ---------------------------------------------------------------------------
extern "C" void kernel_launch(void* const* d_in, const int* in_sizes, int n_in,
                              void* d_out, int out_size) {
    const float* x    = (const float*)d_in[0];
    const float* wk   = (const float*)d_in[1];
    const float* bias = (const float*)d_in[2];
    float* out        = (float*)d_out;

    int npix = BATCH * HW;
    stats1_kernel<<<(npix + 255) / 256, 256>>>(x);
    stats2_kernel<<<(npix + 255) / 256, 256>>>();
    wprep_kernel<<<(WF_WORDS + 255) / 256, 256>>>(wk);

    dim3 grid(HH, 2, BATCH);
    conv_mma_kernel<<<grid, 256>>>(x, bias, out);
}

// round 7
// speedup vs baseline: 8.3819x; 1.3424x over previous
#include <cuda_runtime.h>
#include <cuda_fp16.h>
#include <stdint.h>

#define BATCH 16
#define CIN   128
#define HH    128
#define WW    128
#define OCH   256
#define HW    (HH*WW)
#define KTOT  1152.0f
#define BADCNT 576.0f

// ---------------- scratch (no allocations allowed) ----------------
__device__ float g_pm  [BATCH*HW];
__device__ float g_bad [BATCH*HW];
__device__ float g_csum[BATCH*HW];
__device__ float g_ccnt[BATCH*HW];
// B fragments (single fp16 chain), pre-formatted for mma.sync m16n8k16:
// [ (tap*4+cg)*2+nh ][ nt16 ][ kt2 ][ lane32 ][ reg2 ]  (u32 = 2 fp16)
// per-tcn block = 2048 words = 8192 bytes
#define WF_WORDS (72*2048)
__device__ uint32_t g_wf[WF_WORDS];

__device__ __forceinline__ bool nan_bits(float v) {
    return (__float_as_uint(v) & 0x7fffffffu) > 0x7f800000u;
}
__device__ __forceinline__ uint32_t smem_u32(const void* p) {
    return (uint32_t)__cvta_generic_to_shared(p);
}
__device__ __forceinline__ void cp16(uint32_t dst, const void* src) {
    asm volatile("cp.async.cg.shared.global [%0], [%1], 16;" :: "r"(dst), "l"(src));
}
__device__ __forceinline__ void mma16816(float* c, const uint32_t* a, const uint32_t* b) {
    asm volatile(
        "mma.sync.aligned.m16n8k16.row.col.f32.f16.f16.f32 "
        "{%0,%1,%2,%3}, {%4,%5,%6,%7}, {%8,%9}, {%0,%1,%2,%3};"
        : "+f"(c[0]), "+f"(c[1]), "+f"(c[2]), "+f"(c[3])
        : "r"(a[0]), "r"(a[1]), "r"(a[2]), "r"(a[3]), "r"(b[0]), "r"(b[1]));
}

// ---------------- stats kernels ----------------
__global__ void stats1_kernel(const float* __restrict__ x) {
    int idx = blockIdx.x * blockDim.x + threadIdx.x;
    if (idx >= BATCH * HW) return;
    int b  = idx / HW;
    int hw = idx - b * HW;
    const float* xp = x + (size_t)b * CIN * HW + hw;
    float s = 0.f, cnt = 0.f;
    #pragma unroll 8
    for (int c = 0; c < CIN; c++) {
        float v = xp[(size_t)c * HW];
        bool n = nan_bits(v);
        cnt += n ? 1.f : 0.f;
        s   += n ? 0.f : v;
    }
    g_csum[idx] = s;
    g_ccnt[idx] = cnt;
}

__global__ void stats2_kernel() {
    int idx = blockIdx.x * blockDim.x + threadIdx.x;
    if (idx >= BATCH * HW) return;
    int b  = idx / HW;
    int hw = idx - b * HW;
    int oh = hw / WW;
    int ow = hw - oh * WW;
    float vs = 0.f, cnt = 0.f;
    #pragma unroll
    for (int kh = -1; kh <= 1; kh++) {
        int ih = oh + kh;
        if (ih < 0 || ih >= HH) continue;
        #pragma unroll
        for (int kw = -1; kw <= 1; kw++) {
            int iw = ow + kw;
            if (iw < 0 || iw >= WW) continue;
            int g = b * HW + ih * WW + iw;
            vs  += g_csum[g];
            cnt += g_ccnt[g];
        }
    }
    float valid = KTOT - cnt;
    g_pm[idx]  = vs / fmaxf(valid, 1.f);
    g_bad[idx] = (cnt >= BADCNT) ? 1.f : 0.f;
}

// ---------------- weight prep: fp16 round into mma B-fragment layout ----------------
__global__ void wprep_kernel(const float* __restrict__ w) {
    int idx = blockIdx.x * blockDim.x + threadIdx.x;
    if (idx >= WF_WORDS) return;
    int r     = idx & 1;               // B reg (k-half): b0 k=0..7, b1 k=8..15
    int lane  = (idx >> 1) & 31;
    int kt    = (idx >> 6) & 1;
    int nt    = (idx >> 7) & 15;
    int tcn   = idx >> 11;             // (tap*4+cg)*2+nh
    int nh    = tcn & 1;
    int tapcg = tcn >> 1;
    int cg    = tapcg & 3;
    int tap   = tapcg >> 2;

    int oc = nh * 128 + nt * 8 + (lane >> 2);
    int k0 = (lane & 3) * 2 + r * 8;   // k within 16
    int c0 = cg * 32 + kt * 16 + k0;

    uint32_t pack = 0;
    #pragma unroll
    for (int e = 0; e < 2; e++) {
        float wv = w[((size_t)oc * CIN + (c0 + e)) * 9 + tap];
        pack |= (uint32_t)__half_as_ushort(__float2half_rn(wv)) << (e * 16);
    }
    g_wf[idx] = pack;
}

// ---------------- main conv: fp16 mma.sync implicit GEMM ----------------
// CTA: M=128 pixels (one output row) x N=128 ocs (one half). K=1152.
// 8 warps as 2(m) x 4(n); warp tile 64x32; per-thread 4x4 m16n8 tiles.
#define RAWPAD 34   // fp16 channel stride per column (pad 32->34, conflict-free)

__global__ __launch_bounds__(256, 2)
void conv_mma_kernel(const float* __restrict__ x,
                     const float* __restrict__ bias,
                     float* __restrict__ out)
{
    __shared__ uint16_t s_rawh[132 * RAWPAD]; // fp16 input row, [col][ch] transposed, NaN kept
    __shared__ uint32_t s_af[2048];           // A frags [mt8*kt2][lane32][reg4]
    __shared__ uint32_t s_bf[2048];           // B frags [nt16][kt2][lane32][reg2]
    __shared__ uint16_t s_pmh[128];           // patch mean, fp16
    __shared__ float    s_bad[128], s_bias[128];

    const int tid  = threadIdx.x;
    const int lane = tid & 31;
    const int wid  = tid >> 5;
    const int oh   = blockIdx.x;
    const int nh   = blockIdx.y;
    const int b    = blockIdx.z;

    if (tid < 128) {
        int g = b * HW + oh * WW + tid;
        s_pmh[tid]  = __half_as_ushort(__float2half_rn(g_pm[g]));
        s_bad[tid]  = g_bad[g];
        s_bias[tid] = bias[nh * 128 + tid];
    }

    const int mt0 = (wid >> 2) * 4;   // warp m16-tile base (0 or 4)
    const int nt0 = (wid & 3) * 4;    // warp n8-tile base  (0,4,8,12)

    float acc[4][4][4];
    #pragma unroll
    for (int i = 0; i < 4; i++)
        #pragma unroll
        for (int j = 0; j < 4; j++)
            #pragma unroll
            for (int r = 0; r < 4; r++) acc[i][j][r] = 0.f;

    __syncthreads();  // s_pmh ready

    for (int cg = 0; cg < 4; cg++) {
        for (int kh = 0; kh < 3; kh++) {
            // ---- stage input row as fp16, transposed [col][ch]; NaNs preserved ----
            const int rin = oh + kh - 1;
            const bool rowok = (rin >= 0) & (rin < HH);
            const float* xrow = x + ((size_t)(b * CIN + cg * 32) * HH + rin) * WW;
            for (int i = tid; i < 32 * 132; i += 256) {
                int c   = i / 132;
                int wc  = i - c * 132;
                int col = wc - 1;
                float v = 0.f;
                if (rowok && col >= 0 && col < WW)
                    v = xrow[(size_t)c * HW + col];
                s_rawh[wc * RAWPAD + c] = __half_as_ushort(__float2half_rn(v));
            }
            __syncthreads();

            for (int kw = 0; kw < 3; kw++) {
                const int tap = kh * 3 + kw;
                // ---- B fragments: raw cp.async, 8192 bytes (pre-formatted) ----
                {
                    const char* src = (const char*)g_wf +
                        ((size_t)((tap * 4 + cg) * 2 + nh) * 8192);
                    uint32_t d = smem_u32(s_bf) + (uint32_t)tid * 16u;
                    cp16(d,        src + tid * 16);
                    cp16(d + 4096, src + 4096 + tid * 16);
                    asm volatile("cp.async.commit_group;");
                }
                // ---- A fragments: vector LDS.32 of (k,k+1) + fp16 NaN substitute ----
                // a0:{m, k}  a1:{m+8, k}  a2:{m, k+8}  a3:{m+8, k+8}
                for (int w = tid; w < 2048; w += 256) {
                    int reg  = w & 3;
                    int ln   = (w >> 2) & 31;
                    int tile = w >> 7;            // mt*2 + kt
                    int kt   = tile & 1;
                    int mt   = tile >> 1;
                    int m    = mt * 16 + ((reg & 1) << 3) + (ln >> 2);
                    int k    = kt * 16 + ((reg >> 1) << 3) + (ln & 3) * 2;
                    uint32_t pair = *(const uint32_t*)&s_rawh[(m + kw) * RAWPAD + k];
                    uint32_t pmh  = (uint32_t)s_pmh[m];
                    uint32_t lo = pair & 0xffffu;
                    uint32_t hi = pair >> 16;
                    if ((lo & 0x7fffu) > 0x7c00u) lo = pmh;
                    if ((hi & 0x7fffu) > 0x7c00u) hi = pmh;
                    s_af[w] = (hi << 16) | lo;
                }
                asm volatile("cp.async.wait_group 0;");
                __syncthreads();

                // ---- MMA: K=32 (2 k16 steps), single fp16 chain ----
                #pragma unroll
                for (int kt = 0; kt < 2; kt++) {
                    uint32_t a[4][4];
                    #pragma unroll
                    for (int i = 0; i < 4; i++) {
                        uint4 av = *(const uint4*)&s_af[(((mt0 + i) * 2 + kt) * 32 + lane) * 4];
                        a[i][0] = av.x; a[i][1] = av.y; a[i][2] = av.z; a[i][3] = av.w;
                    }
                    #pragma unroll
                    for (int j = 0; j < 4; j++) {
                        uint2 bv = *(const uint2*)
                            &s_bf[(((nt0 + j) * 2 + kt) * 32 + lane) * 2];
                        uint32_t bb[2] = {bv.x, bv.y};
                        #pragma unroll
                        for (int i = 0; i < 4; i++)
                            mma16816(acc[i][j], a[i], bb);
                    }
                }
                __syncthreads();   // protect s_af/s_bf (and s_rawh at kh turn)
            }
        }
    }

    // ---- epilogue: bias + bad->NaN, direct stores ----
    const float NANF = __uint_as_float(0x7fc00000u);
    #pragma unroll
    for (int i = 0; i < 4; i++) {
        #pragma unroll
        for (int r = 0; r < 4; r++) {
            int m = (mt0 + i) * 16 + ((r >> 1) << 3) + (lane >> 2);
            bool isbad = s_bad[m] != 0.f;
            #pragma unroll
            for (int j = 0; j < 4; j++) {
                int n  = (nt0 + j) * 8 + (lane & 3) * 2 + (r & 1);
                int oc = nh * 128 + n;
                float v = acc[i][j][r] + s_bias[n];
                out[(((size_t)b * OCH + oc) * HH + oh) * WW + m] = isbad ? NANF : v;
            }
        }
    }
}

// ---------------------------------------------------------------------------
extern "C" void kernel_launch(void* const* d_in, const int* in_sizes, int n_in,
                              void* d_out, int out_size) {
    const float* x    = (const float*)d_in[0];
    const float* wk   = (const float*)d_in[1];
    const float* bias = (const float*)d_in[2];
    float* out        = (float*)d_out;

    int npix = BATCH * HW;
    stats1_kernel<<<(npix + 255) / 256, 256>>>(x);
    stats2_kernel<<<(npix + 255) / 256, 256>>>();
    wprep_kernel<<<(WF_WORDS + 255) / 256, 256>>>(wk);

    dim3 grid(HH, 2, BATCH);
    conv_mma_kernel<<<grid, 256>>>(x, bias, out);
}

// round 8
// speedup vs baseline: 10.7354x; 1.2808x over previous
#include <cuda_runtime.h>
#include <cuda_fp16.h>
#include <stdint.h>

#define BATCH 16
#define CIN   128
#define HH    128
#define WW    128
#define OCH   256
#define HW    (HH*WW)
#define KTOT  1152.0f
#define BADCNT 576.0f

// ---------------- scratch (no allocations allowed) ----------------
__device__ float g_pm  [BATCH*HW];
__device__ float g_bad [BATCH*HW];
__device__ float g_csum[BATCH*HW];
__device__ float g_ccnt[BATCH*HW];
// B fragments (single fp16 chain) for mma.sync m16n8k16:
// [ tap*4+cg ][ nt32 ][ kt2 ][ lane32 ][ reg2 ]  (u32 = 2 fp16); block = 4096 words
#define WF_WORDS (36*4096)
__device__ uint32_t g_wf[WF_WORDS];

__device__ __forceinline__ bool nan_bits(float v) {
    return (__float_as_uint(v) & 0x7fffffffu) > 0x7f800000u;
}
__device__ __forceinline__ uint32_t smem_u32(const void* p) {
    return (uint32_t)__cvta_generic_to_shared(p);
}
__device__ __forceinline__ void cp16(uint32_t dst, const void* src) {
    asm volatile("cp.async.cg.shared.global [%0], [%1], 16;" :: "r"(dst), "l"(src));
}
__device__ __forceinline__ void mma16816(float* c, const uint32_t* a, const uint32_t* b) {
    asm volatile(
        "mma.sync.aligned.m16n8k16.row.col.f32.f16.f16.f32 "
        "{%0,%1,%2,%3}, {%4,%5,%6,%7}, {%8,%9}, {%0,%1,%2,%3};"
        : "+f"(c[0]), "+f"(c[1]), "+f"(c[2]), "+f"(c[3])
        : "r"(a[0]), "r"(a[1]), "r"(a[2]), "r"(a[3]), "r"(b[0]), "r"(b[1]));
}

// ---------------- stats kernels ----------------
__global__ void stats1_kernel(const float* __restrict__ x) {
    int idx = blockIdx.x * blockDim.x + threadIdx.x;
    if (idx >= BATCH * HW) return;
    int b  = idx / HW;
    int hw = idx - b * HW;
    const float* xp = x + (size_t)b * CIN * HW + hw;
    float s = 0.f, cnt = 0.f;
    #pragma unroll 8
    for (int c = 0; c < CIN; c++) {
        float v = xp[(size_t)c * HW];
        bool n = nan_bits(v);
        cnt += n ? 1.f : 0.f;
        s   += n ? 0.f : v;
    }
    g_csum[idx] = s;
    g_ccnt[idx] = cnt;
}

__global__ void stats2_kernel() {
    int idx = blockIdx.x * blockDim.x + threadIdx.x;
    if (idx >= BATCH * HW) return;
    int b  = idx / HW;
    int hw = idx - b * HW;
    int oh = hw / WW;
    int ow = hw - oh * WW;
    float vs = 0.f, cnt = 0.f;
    #pragma unroll
    for (int kh = -1; kh <= 1; kh++) {
        int ih = oh + kh;
        if (ih < 0 || ih >= HH) continue;
        #pragma unroll
        for (int kw = -1; kw <= 1; kw++) {
            int iw = ow + kw;
            if (iw < 0 || iw >= WW) continue;
            int g = b * HW + ih * WW + iw;
            vs  += g_csum[g];
            cnt += g_ccnt[g];
        }
    }
    float valid = KTOT - cnt;
    g_pm[idx]  = vs / fmaxf(valid, 1.f);
    g_bad[idx] = (cnt >= BADCNT) ? 1.f : 0.f;
}

// ---------------- weight prep: fp16 round into B-fragment layout ----------------
__global__ void wprep_kernel(const float* __restrict__ w) {
    int idx = blockIdx.x * blockDim.x + threadIdx.x;
    if (idx >= WF_WORDS) return;
    int r    = idx & 1;                // k-half: r0 k=0..7, r1 k=8..15
    int lane = (idx >> 1) & 31;
    int kt   = (idx >> 6) & 1;
    int nt   = (idx >> 7) & 31;
    int tcg  = idx >> 12;              // tap*4+cg
    int cg   = tcg & 3;
    int tap  = tcg >> 2;

    int oc = nt * 8 + (lane >> 2);
    int c0 = cg * 32 + kt * 16 + (lane & 3) * 2 + r * 8;

    uint32_t pack = 0;
    #pragma unroll
    for (int e = 0; e < 2; e++) {
        float wv = w[((size_t)oc * CIN + (c0 + e)) * 9 + tap];
        pack |= (uint32_t)__half_as_ushort(__float2half_rn(wv)) << (e * 16);
    }
    g_wf[idx] = pack;
}

// ---------------- main conv: pipelined fp16 mma.sync implicit GEMM ----------------
// CTA: 512 thr, 16 warps (2m x 8n). M=128 pixels (one row) x N=256 ocs. K=1152.
#define THREADS 512
#define RAWPAD 34
#define RAWELEMS (132*RAWPAD)     // 4488 u16 = 8976 B

#define OFF_BF   0u               // 2 x 16384
#define OFF_AF   32768u           // 2 x 8192
#define OFF_RAW  49152u           // 2 x 8976
#define OFF_PMH  67104u           // 256
#define OFF_BAD  67360u           // 512
#define OFF_BIAS 67872u           // 1024
#define SMEMSZ   68896u

__device__ __forceinline__ void stage_row(uint16_t* raw, const float* __restrict__ x,
                                          int b, int oh, int R, int tid) {
    int cg = R / 3, kh = R - cg * 3;
    int rin = oh + kh - 1;
    bool rowok = (rin >= 0) & (rin < HH);
    const float* xrow = x + ((size_t)(b * CIN + cg * 32) * HH + rin) * WW;
    #pragma unroll
    for (int it = 0; it < 9; it++) {
        int i = tid + it * THREADS;
        if (i < 32 * 132) {
            int c   = i / 132;
            int wc  = i - c * 132;
            int col = wc - 1;
            float v = 0.f;
            if (rowok && col >= 0 && col < WW) v = xrow[(size_t)c * HW + col];
            raw[wc * RAWPAD + c] = __half_as_ushort(__float2half_rn(v));
        }
    }
}

__device__ __forceinline__ void build_af(uint32_t* af, const uint16_t* raw,
                                         const uint16_t* pmh, int kw, int tid) {
    // a0:{m,k} a1:{m+8,k} a2:{m,k+8} a3:{m+8,k+8}
    #pragma unroll
    for (int it = 0; it < 4; it++) {
        int w    = tid + it * THREADS;
        int reg  = w & 3;
        int ln   = (w >> 2) & 31;
        int tile = w >> 7;            // mt*2 + kt
        int kt   = tile & 1;
        int mt   = tile >> 1;
        int m    = mt * 16 + ((reg & 1) << 3) + (ln >> 2);
        int k    = kt * 16 + ((reg >> 1) << 3) + (ln & 3) * 2;
        uint32_t pair = *(const uint32_t*)&raw[(m + kw) * RAWPAD + k];
        uint32_t pmv  = (uint32_t)pmh[m];
        uint32_t lo = pair & 0xffffu, hi = pair >> 16;
        if ((lo & 0x7fffu) > 0x7c00u) lo = pmv;
        if ((hi & 0x7fffu) > 0x7c00u) hi = pmv;
        af[w] = (hi << 16) | lo;
    }
}

__device__ __forceinline__ void issue_bf(uint32_t bf_addr, int R, int kw, int tid) {
    int cg  = R / 3, kh = R - cg * 3;
    int tcg = (kh * 3 + kw) * 4 + cg;
    const char* src = (const char*)g_wf + (size_t)tcg * 16384;
    uint32_t d = bf_addr + (uint32_t)tid * 16u;
    cp16(d,        src + tid * 16);
    cp16(d + 8192, src + 8192 + tid * 16);
    asm volatile("cp.async.commit_group;");
}

__device__ __forceinline__ void mma_tap(float acc[4][4][4], const uint32_t* af,
                                        const uint32_t* bf, int mt0, int nt0, int lane) {
    #pragma unroll
    for (int kt = 0; kt < 2; kt++) {
        uint32_t a[4][4];
        #pragma unroll
        for (int i = 0; i < 4; i++) {
            uint4 av = *(const uint4*)&af[(((mt0 + i) * 2 + kt) * 32 + lane) * 4];
            a[i][0] = av.x; a[i][1] = av.y; a[i][2] = av.z; a[i][3] = av.w;
        }
        #pragma unroll
        for (int j = 0; j < 4; j++) {
            uint2 bv = *(const uint2*)&bf[(((nt0 + j) * 2 + kt) * 32 + lane) * 2];
            uint32_t bb[2] = {bv.x, bv.y};
            #pragma unroll
            for (int i = 0; i < 4; i++)
                mma16816(acc[i][j], a[i], bb);
        }
    }
}

__global__ __launch_bounds__(THREADS, 1)
void conv_mma_kernel(const float* __restrict__ x,
                     const float* __restrict__ bias,
                     float* __restrict__ out)
{
    extern __shared__ char sm[];
    uint32_t* s_bfb[2] = {(uint32_t*)(sm + OFF_BF), (uint32_t*)(sm + OFF_BF + 16384)};
    uint32_t* s_afb[2] = {(uint32_t*)(sm + OFF_AF), (uint32_t*)(sm + OFF_AF + 8192)};
    uint16_t* s_rawb[2] = {(uint16_t*)(sm + OFF_RAW), (uint16_t*)(sm + OFF_RAW + 8976)};
    uint16_t* s_pmh  = (uint16_t*)(sm + OFF_PMH);
    float*    s_bad  = (float*)(sm + OFF_BAD);
    float*    s_bias = (float*)(sm + OFF_BIAS);
    const uint32_t smb = smem_u32(sm);

    const int tid  = threadIdx.x;
    const int lane = tid & 31;
    const int wid  = tid >> 5;
    const int oh   = blockIdx.x;
    const int b    = blockIdx.y;
    const int mt0  = (wid >> 3) * 4;   // 0 or 4
    const int nt0  = (wid & 7) * 4;    // 0,4,...,28

    if (tid < 128) {
        int g = b * HW + oh * WW + tid;
        s_pmh[tid] = __half_as_ushort(__float2half_rn(g_pm[g]));
        s_bad[tid] = g_bad[g];
    }
    if (tid < 256) s_bias[tid] = bias[tid];

    float acc[4][4][4];
    #pragma unroll
    for (int i = 0; i < 4; i++)
        #pragma unroll
        for (int j = 0; j < 4; j++)
            #pragma unroll
            for (int r = 0; r < 4; r++) acc[i][j][r] = 0.f;

    // prologue: stage row 0, build tap (0,0) into buffer 0
    stage_row(s_rawb[0], x, b, oh, 0, tid);
    __syncthreads();
    issue_bf(smb + OFF_BF, 0, 0, tid);
    build_af(s_afb[0], s_rawb[0], s_pmh, 0, tid);
    asm volatile("cp.async.wait_group 0;");
    __syncthreads();

    int p = 0;
    for (int R = 0; R < 12; R++) {
        // phase A: mma (R,0) || build (R,1)
        issue_bf(smb + OFF_BF + (uint32_t)(p ^ 1) * 16384u, R, 1, tid);
        build_af(s_afb[p ^ 1], s_rawb[R & 1], s_pmh, 1, tid);
        mma_tap(acc, s_afb[p], s_bfb[p], mt0, nt0, lane);
        asm volatile("cp.async.wait_group 0;");
        __syncthreads();
        p ^= 1;
        // phase B: mma (R,1) || build (R,2) || restage row R+1
        issue_bf(smb + OFF_BF + (uint32_t)(p ^ 1) * 16384u, R, 2, tid);
        build_af(s_afb[p ^ 1], s_rawb[R & 1], s_pmh, 2, tid);
        if (R < 11) stage_row(s_rawb[(R + 1) & 1], x, b, oh, R + 1, tid);
        mma_tap(acc, s_afb[p], s_bfb[p], mt0, nt0, lane);
        asm volatile("cp.async.wait_group 0;");
        __syncthreads();
        p ^= 1;
        // phase C: mma (R,2) || build (R+1,0)
        if (R < 11) {
            issue_bf(smb + OFF_BF + (uint32_t)(p ^ 1) * 16384u, R + 1, 0, tid);
            build_af(s_afb[p ^ 1], s_rawb[(R + 1) & 1], s_pmh, 0, tid);
        }
        mma_tap(acc, s_afb[p], s_bfb[p], mt0, nt0, lane);
        asm volatile("cp.async.wait_group 0;");
        __syncthreads();
        p ^= 1;
    }

    // ---- epilogue: bias + bad->NaN, direct stores ----
    const float NANF = __uint_as_float(0x7fc00000u);
    #pragma unroll
    for (int i = 0; i < 4; i++) {
        #pragma unroll
        for (int r = 0; r < 4; r++) {
            int m = (mt0 + i) * 16 + ((r >> 1) << 3) + (lane >> 2);
            bool isbad = s_bad[m] != 0.f;
            #pragma unroll
            for (int j = 0; j < 4; j++) {
                int n = (nt0 + j) * 8 + (lane & 3) * 2 + (r & 1);
                float v = acc[i][j][r] + s_bias[n];
                out[(((size_t)b * OCH + n) * HH + oh) * WW + m] = isbad ? NANF : v;
            }
        }
    }
}

// ---------------------------------------------------------------------------
extern "C" void kernel_launch(void* const* d_in, const int* in_sizes, int n_in,
                              void* d_out, int out_size) {
    const float* x    = (const float*)d_in[0];
    const float* wk   = (const float*)d_in[1];
    const float* bias = (const float*)d_in[2];
    float* out        = (float*)d_out;

    int npix = BATCH * HW;
    stats1_kernel<<<(npix + 255) / 256, 256>>>(x);
    stats2_kernel<<<(npix + 255) / 256, 256>>>();
    wprep_kernel<<<(WF_WORDS + 255) / 256, 256>>>(wk);

    cudaFuncSetAttribute(conv_mma_kernel,
                         cudaFuncAttributeMaxDynamicSharedMemorySize, SMEMSZ);
    dim3 grid(HH, BATCH);
    conv_mma_kernel<<<grid, THREADS, SMEMSZ>>>(x, bias, out);
}